// round 3
// baseline (speedup 1.0000x reference)
#include <cuda_runtime.h>
#include <cstdint>

// Problem constants (from reference)
#define Bk 4
#define Ck 256
#define Hk 96
#define Wk 160
#define HWk (Hk * Wk)            // 15360
#define Dk 4
#define PPk 81

// Tiling
#define TW 32                    // tile width (pixels)
#define TH 8                     // tile height (pixels)
#define KC 8                     // channels per chunk
#define NCH (Ck / KC)            // 32 chunks
#define NTHREADS 288             // 9 warps: warp w handles dy = w-4

// Padded shared rows (bank-conflict-free for the 2-row LDS.128 phases)
#define S0R 36                   // f0 tile row: 32 cols + pad
#define S1R 44                   // f1 tile row: 40 cols + pad
#define S0SZ (KC * TH * S0R)     // 2304 floats
#define S1SZ (KC * 16 * S1R)     // 5632 floats
#define BUFSZ (S0SZ + S1SZ)      // 7936 floats
#define SMEM_FLOATS (2 * BUFSZ)  // double buffered: 15872 floats = 63488 B

__device__ __forceinline__ void cp_async16(unsigned saddr, const void* g) {
    asm volatile("cp.async.cg.shared.global [%0], [%1], 16;\n" ::"r"(saddr), "l"(g));
}
__device__ __forceinline__ void cp_async8(unsigned saddr, const void* g, int sz) {
    // sz = 8 (copy) or 0 (zero-fill, no gmem read)
    asm volatile("cp.async.ca.shared.global [%0], [%1], 8, %2;\n" ::"r"(saddr), "l"(g), "r"(sz));
}

// ---- packed f32x2 helpers (ptxas never auto-fuses FFMA2; PTX-only) ----
__device__ __forceinline__ unsigned long long pk2(float lo, float hi) {
    unsigned long long r;
    asm("mov.b64 %0, {%1, %2};" : "=l"(r) : "f"(lo), "f"(hi));
    return r;
}
__device__ __forceinline__ void fma2(unsigned long long& d, unsigned long long a,
                                     unsigned long long b) {
    asm("fma.rn.f32x2 %0, %1, %2, %0;" : "+l"(d) : "l"(a), "l"(b));
}
__device__ __forceinline__ float2 upk(unsigned long long v) {
    float2 r;
    asm("mov.b64 {%0, %1}, %2;" : "=f"(r.x), "=f"(r.y) : "l"(v));
    return r;
}

__global__ void __launch_bounds__(NTHREADS)
corr_kernel(const float* __restrict__ f0, const float* __restrict__ f1,
            float* __restrict__ out) {
    extern __shared__ float smem[];

    const int t    = threadIdx.x;
    const int x0   = blockIdx.x * TW;
    const int y0   = blockIdx.y * TH;
    const int b    = blockIdx.z;

    const int warp = t >> 5;      // 0..8  -> dy = warp - 4
    const int lane = t & 31;
    const int r    = lane >> 2;   // 0..7  tile row
    const int xs   = lane & 3;    // 0..3  x-segment (8 px each)

    const float* f0b = f0 + (size_t)b * Ck * HWk;
    const float* f1b = f1 + (size_t)b * Ck * HWk;

    // acc2[p][j]: packed pair (px=2p, px=2p+1) for displacement column j
    unsigned long long acc2[4][9];
#pragma unroll
    for (int p = 0; p < 4; p++)
#pragma unroll
        for (int j = 0; j < 9; j++) acc2[p][j] = 0ull;

    // ---- cooperative chunk prefetch (cp.async, zero-fill halo) ----
    auto prefetch = [&](int c0, int bsel) {
        float* s0 = smem + bsel * BUFSZ;
        float* s1 = s0 + S0SZ;
        // f0 tile: KC x TH x 32  -> 512 float4 transfers
#pragma unroll
        for (int i = 0; i < 2; i++) {
            int idx = t + i * NTHREADS;
            if (idx < 512) {
                int c   = idx >> 6;           // /64
                int rem = idx & 63;
                int row = rem >> 3;
                int col = (rem & 7) << 2;
                const float* g = f0b + ((size_t)(c0 + c) * Hk + (y0 + row)) * Wk + x0 + col;
                unsigned sa = (unsigned)__cvta_generic_to_shared(s0 + (c * TH + row) * S0R + col);
                cp_async16(sa, g);
            }
        }
        // f1 tile: KC x 16 x 40 -> 2560 float2 transfers (x0-4 is even -> 8B aligned)
#pragma unroll
        for (int i = 0; i < 9; i++) {
            int idx = t + i * NTHREADS;
            if (idx < 2560) {
                int c    = idx / 320;
                int rem  = idx - c * 320;
                int row  = rem / 20;          // 0..15
                int col2 = rem - row * 20;    // 0..19
                int col  = col2 * 2;          // 0..38
                int gy   = y0 - 4 + row;
                int gx   = x0 - 4 + col;      // even; pair (gx,gx+1) uniformly in/out of bounds
                bool ok  = (gy >= 0) && (gy < Hk) && (gx >= 0) && (gx < Wk);
                int gyc  = gy < 0 ? 0 : (gy >= Hk ? Hk - 1 : gy);
                int gxc  = gx < 0 ? 0 : (gx >= Wk ? Wk - 2 : gx);
                const float* g = f1b + ((size_t)(c0 + c) * Hk + gyc) * Wk + gxc;
                unsigned sa = (unsigned)__cvta_generic_to_shared(s1 + (c * 16 + row) * S1R + col);
                cp_async8(sa, g, ok ? 8 : 0);
            }
        }
        asm volatile("cp.async.commit_group;\n" ::: "memory");
    };

    prefetch(0, 0);

#pragma unroll 1
    for (int k = 0; k < NCH; k++) {
        if (k + 1 < NCH) {
            prefetch((k + 1) * KC, (k + 1) & 1);
            asm volatile("cp.async.wait_group 1;\n" ::: "memory");
        } else {
            asm volatile("cp.async.wait_group 0;\n" ::: "memory");
        }
        __syncthreads();

        const float* s0 = smem + (k & 1) * BUFSZ;
        const float* s1 = s0 + S0SZ;

#pragma unroll
        for (int c = 0; c < KC; c++) {
            // 16-float f1 window for this (dy, row, xseg): rows r+warp in [0,16)
            const float* wp = s1 + (c * 16 + r + warp) * S1R + xs * 8;
            float4 w0 = *(const float4*)&wp[0];
            float4 w1 = *(const float4*)&wp[4];
            float4 w2 = *(const float4*)&wp[8];
            float4 w3 = *(const float4*)&wp[12];
            // 8 f0 pixels
            const float* fp = s0 + (c * TH + r) * S0R + xs * 8;
            float4 a0 = *(const float4*)&fp[0];
            float4 a1 = *(const float4*)&fp[4];

            // a pairs (aligned halves of LDS.128 -> movs should coalesce)
            unsigned long long aP[4] = {
                pk2(a0.x, a0.y), pk2(a0.z, a0.w),
                pk2(a1.x, a1.y), pk2(a1.z, a1.w)};
            // aligned window pairs wA[k] = (w[2k], w[2k+1])
            unsigned long long wA[8] = {
                pk2(w0.x, w0.y), pk2(w0.z, w0.w),
                pk2(w1.x, w1.y), pk2(w1.z, w1.w),
                pk2(w2.x, w2.y), pk2(w2.z, w2.w),
                pk2(w3.x, w3.y), pk2(w3.z, w3.w)};
            // shifted window pairs wS[k] = (w[2k+1], w[2k+2])
            unsigned long long wS[7] = {
                pk2(w0.y, w0.z), pk2(w0.w, w1.x),
                pk2(w1.y, w1.z), pk2(w1.w, w2.x),
                pk2(w2.y, w2.z), pk2(w2.w, w3.x),
                pk2(w3.y, w3.z)};

#pragma unroll
            for (int p = 0; p < 4; p++) {
#pragma unroll
                for (int j = 0; j < 9; j++) {
                    if ((j & 1) == 0)
                        fma2(acc2[p][j], aP[p], wA[p + (j >> 1)]);
                    else
                        fma2(acc2[p][j], aP[p], wS[p + ((j - 1) >> 1)]);
                }
            }
        }
        __syncthreads();
    }

    // ---- epilogue: out[b, warp*9+j, y0+r, x0+xs*8+px] ----
    float* ob = out + (((size_t)b * PPk + warp * 9) * Hk + (y0 + r)) * Wk + x0 + xs * 8;
#pragma unroll
    for (int j = 0; j < 9; j++) {
        float* p = ob + (size_t)j * HWk;
        float2 u0 = upk(acc2[0][j]);
        float2 u1 = upk(acc2[1][j]);
        float2 u2 = upk(acc2[2][j]);
        float2 u3 = upk(acc2[3][j]);
        *(float4*)p       = make_float4(u0.x, u0.y, u1.x, u1.y);
        *((float4*)p + 1) = make_float4(u2.x, u2.y, u3.x, u3.y);
    }
}

extern "C" void kernel_launch(void* const* d_in, const int* in_sizes, int n_in,
                              void* d_out, int out_size) {
    const float* f0 = (const float*)d_in[0];
    const float* f1 = (const float*)d_in[1];
    float* out      = (float*)d_out;

    const int smem_bytes = SMEM_FLOATS * sizeof(float);  // 63488
    cudaFuncSetAttribute(corr_kernel, cudaFuncAttributeMaxDynamicSharedMemorySize, smem_bytes);

    dim3 grid(Wk / TW, Hk / TH, Bk);  // (5, 12, 4) = 240 blocks
    corr_kernel<<<grid, NTHREADS, smem_bytes>>>(f0, f1, out);
}

// round 4
// speedup vs baseline: 1.0995x; 1.0995x over previous
#include <cuda_runtime.h>
#include <cstdint>

// Problem constants
#define Bk 4
#define Ck 256
#define Hk 96
#define Wk 160
#define HWk (Hk * Wk)            // 15360
#define PPk 81

// Tiling: 32x8 pixel tile, 18 warps = (9 dy) x (2 x-halves), 4 px/thread
#define TW 32
#define TH 8
#define KC 8                     // channels per chunk
#define NCH (Ck / KC)            // 32 chunks
#define NTHREADS 576             // 18 warps

// Shared strides: row stride 48 floats => consecutive rows 16 banks apart,
// conflict-free for the 8-lane LDS.128 phases (rows {r,r+1} x 4 xq).
#define S0R 48                   // f0 row (32 used)
#define S1R 48                   // f1 halo row (40 used)
#define S0SZ (KC * TH * S0R)     // 3072 floats
#define S1SZ (KC * 16 * S1R)     // 6144 floats
#define BUFSZ (S0SZ + S1SZ)      // 9216 floats
#define SMEM_FLOATS (2 * BUFSZ)  // 18432 floats = 73728 B

__device__ __forceinline__ void cp_async16(unsigned saddr, const void* g) {
    asm volatile("cp.async.cg.shared.global [%0], [%1], 16;\n" ::"r"(saddr), "l"(g));
}
__device__ __forceinline__ void cp_async8(unsigned saddr, const void* g, int sz) {
    asm volatile("cp.async.ca.shared.global [%0], [%1], 8, %2;\n" ::"r"(saddr), "l"(g), "r"(sz));
}

__global__ void __launch_bounds__(NTHREADS)
corr_kernel(const float* __restrict__ f0, const float* __restrict__ f1,
            float* __restrict__ out) {
    extern __shared__ float smem[];

    const int t    = threadIdx.x;
    const int x0   = blockIdx.x * TW;
    const int y0   = blockIdx.y * TH;
    const int b    = blockIdx.z;

    const int warp = t >> 5;                 // 0..17
    const int lane = t & 31;
    const int dyw  = (warp >= 9) ? warp - 9 : warp;  // 0..8 -> dy = dyw-4
    const int half = (warp >= 9) ? 1 : 0;            // x half
    const int r    = lane >> 2;              // 0..7 tile row
    const int xq   = lane & 3;               // 0..3
    const int xoff = half * 16 + xq * 4;     // 0..28, multiple of 4

    const float* f0b = f0 + (size_t)b * Ck * HWk;
    const float* f1b = f1 + (size_t)b * Ck * HWk;

    float acc[4][9];
#pragma unroll
    for (int p = 0; p < 4; p++)
#pragma unroll
        for (int j = 0; j < 9; j++) acc[p][j] = 0.0f;

    // ---- cooperative chunk prefetch (cp.async, zero-fill halo) ----
    auto prefetch = [&](int c0, int bsel) {
        float* s0 = smem + bsel * BUFSZ;
        float* s1 = s0 + S0SZ;
        // f0 tile: KC x TH x 32 -> 512 float4 transfers (threads 0..511)
        if (t < 512) {
            int c   = t >> 6;
            int rem = t & 63;
            int row = rem >> 3;
            int col = (rem & 7) << 2;
            const float* g = f0b + ((size_t)(c0 + c) * Hk + (y0 + row)) * Wk + x0 + col;
            unsigned sa = (unsigned)__cvta_generic_to_shared(s0 + (c * TH + row) * S0R + col);
            cp_async16(sa, g);
        }
        // f1 halo: KC x 16 x 40 -> 2560 float2 transfers
#pragma unroll
        for (int i = 0; i < 5; i++) {
            int idx = t + i * NTHREADS;
            if (idx < 2560) {
                int c    = idx / 320;
                int rem  = idx - c * 320;
                int row  = rem / 20;          // 0..15
                int col2 = rem - row * 20;    // 0..19
                int col  = col2 * 2;          // 0..38
                int gy   = y0 - 4 + row;
                int gx   = x0 - 4 + col;      // even; pair uniformly in/out of bounds
                bool ok  = (gy >= 0) && (gy < Hk) && (gx >= 0) && (gx < Wk);
                int gyc  = gy < 0 ? 0 : (gy >= Hk ? Hk - 1 : gy);
                int gxc  = gx < 0 ? 0 : (gx >= Wk ? Wk - 2 : gx);
                const float* g = f1b + ((size_t)(c0 + c) * Hk + gyc) * Wk + gxc;
                unsigned sa = (unsigned)__cvta_generic_to_shared(s1 + (c * 16 + row) * S1R + col);
                cp_async8(sa, g, ok ? 8 : 0);
            }
        }
        asm volatile("cp.async.commit_group;\n" ::: "memory");
    };

    prefetch(0, 0);

#pragma unroll 1
    for (int k = 0; k < NCH; k++) {
        if (k + 1 < NCH) {
            prefetch((k + 1) * KC, (k + 1) & 1);
            asm volatile("cp.async.wait_group 1;\n" ::: "memory");
        } else {
            asm volatile("cp.async.wait_group 0;\n" ::: "memory");
        }
        __syncthreads();

        const float* s0 = smem + (k & 1) * BUFSZ;
        const float* s1 = s0 + S0SZ;

#pragma unroll
        for (int c = 0; c < KC; c++) {
            // 12-float f1 window: halo row r+dyw, cols xoff..xoff+11
            float w[12];
            const float* wp = s1 + (c * 16 + r + dyw) * S1R + xoff;
            *(float4*)&w[0] = *(const float4*)&wp[0];
            *(float4*)&w[4] = *(const float4*)&wp[4];
            *(float4*)&w[8] = *(const float4*)&wp[8];
            // 4 f0 pixels
            float a[4];
            const float* fp = s0 + (c * TH + r) * S0R + xoff;
            *(float4*)&a[0] = *(const float4*)&fp[0];
#pragma unroll
            for (int p = 0; p < 4; p++)
#pragma unroll
                for (int j = 0; j < 9; j++)
                    acc[p][j] = fmaf(a[p], w[p + j], acc[p][j]);
        }
        __syncthreads();
    }

    // ---- epilogue: out[b, dyw*9+j, y0+r, x0+xoff+p] ----
    float* ob = out + (((size_t)b * PPk + dyw * 9) * Hk + (y0 + r)) * Wk + x0 + xoff;
#pragma unroll
    for (int j = 0; j < 9; j++) {
        float* p = ob + (size_t)j * HWk;
        *(float4*)p = make_float4(acc[0][j], acc[1][j], acc[2][j], acc[3][j]);
    }
}

extern "C" void kernel_launch(void* const* d_in, const int* in_sizes, int n_in,
                              void* d_out, int out_size) {
    const float* f0 = (const float*)d_in[0];
    const float* f1 = (const float*)d_in[1];
    float* out      = (float*)d_out;

    const int smem_bytes = SMEM_FLOATS * sizeof(float);  // 73728
    cudaFuncSetAttribute(corr_kernel, cudaFuncAttributeMaxDynamicSharedMemorySize, smem_bytes);

    dim3 grid(Wk / TW, Hk / TH, Bk);  // (5, 12, 4) = 240 blocks
    corr_kernel<<<grid, NTHREADS, smem_bytes>>>(f0, f1, out);
}